// round 14
// baseline (speedup 1.0000x reference)
#include <cuda_runtime.h>
#include <math.h>

#define NB 16
#define CH 3
#define HGT 512
#define WID 512
#define HW (HGT*WID)          // 262144

#define TW 256                // tile width (outputs)
#define TH 16                 // tile height (outputs)
#define NTHR 160              // 5 warps; 132 loader threads, 128 output threads
#define HALO 264              // staged halo columns: bx-4 .. bx+259
#define NBLOCKS (NB * (HGT/TH) * (WID/TW))   // 1024

// Per-image accumulators + completion counter. Zero-initialized at load;
// the last block resets everything so each graph replay starts clean.
__device__ double   g_S[NB];
__device__ double   g_SS[NB];
__device__ double   g_WR[NB];
__device__ unsigned g_done;

__device__ __forceinline__ int reflect_idx(int i, int n) {
    if (i < 0)  return -i;
    if (i >= n) return 2*n - 2 - i;
    return i;
}

// ---------------------------------------------------------------------------
// Fused: residual on-the-fly + 7x7 local unbiased variance (reflect) +
// per-image S/SS/WR + final loss in last block.
// Tile 256x16, halo 264x22 -> traffic amplification 1.42 (vs 1.75 at 512x8).
// Loader threads (tid<132): one float2 column pair each, register ring of 7
// rows, vertical (sum,sumsq) staged to smem 4 rows at a time.
// Output threads (tid<128): horizontal 7-tap from smem, 2 output cols each.
// Grid (2,32,16)=1024 blocks; 7 blocks/SM -> single wave on 148 SMs.
// ---------------------------------------------------------------------------
__global__ __launch_bounds__(NTHR, 7) void fused_kernel(
    const float* __restrict__ pred, const float* __restrict__ targ,
    float* __restrict__ out)
{
    const int n   = blockIdx.z;
    const int bx  = blockIdx.x * TW;
    const int by  = blockIdx.y * TH;
    const int tid = threadIdx.x;

    __shared__ float sVs[4][HALO + 2];   // 7-row column sums
    __shared__ float sVq[4][HALO + 2];   // 7-row column sums of squares
    __shared__ float sC [4][HALO + 2];   // center-row residual
    __shared__ float red[3][5];
    __shared__ int   sLast;

    const float* __restrict__ p0 = pred + (size_t)n * CH * HW;
    const float* __restrict__ t0 = targ + (size_t)n * CH * HW;

    const bool loader = (tid < 132);
    const int  hc     = bx - 4 + 2 * tid;            // first of 2 halo cols
    const bool inb    = (hc >= 0) && (hc <= WID - 2);
    const int  gx0    = reflect_idx(hc,     WID);    // used only when !inb
    const int  gx1    = reflect_idx(hc + 1, WID);
    const bool statAct = (tid >= 2) && (tid < 130);  // cols bx..bx+255
    const bool outAct  = (tid < 128);

    float2 ring[7];
    float s_acc = 0.f, ss_acc = 0.f, wr_acc = 0.f;

    // Prefill ring slots 1..6 with logical rows by-3 .. by+2.
    if (loader) {
        #pragma unroll
        for (int k = 0; k < 6; ++k) {
            const int yr = by - 3 + k;
            const int gy = reflect_idx(yr, HGT);
            const int rowb = gy * WID;
            float2 r;
            if (inb) {
                const int idx = rowb + hc;
                float2 pa = *(const float2*)(p0 + idx);
                float2 ta = *(const float2*)(t0 + idx);
                float2 pb = *(const float2*)(p0 + HW + idx);
                float2 tb = *(const float2*)(t0 + HW + idx);
                float2 pc = *(const float2*)(p0 + 2*HW + idx);
                float2 tc = *(const float2*)(t0 + 2*HW + idx);
                r.x = fabsf(pa.x - ta.x) + fabsf(pb.x - tb.x) + fabsf(pc.x - tc.x);
                r.y = fabsf(pa.y - ta.y) + fabsf(pb.y - tb.y) + fabsf(pc.y - tc.y);
            } else {
                r.x = fabsf(p0[rowb+gx0]      - t0[rowb+gx0])
                    + fabsf(p0[HW+rowb+gx0]   - t0[HW+rowb+gx0])
                    + fabsf(p0[2*HW+rowb+gx0] - t0[2*HW+rowb+gx0]);
                r.y = fabsf(p0[rowb+gx1]      - t0[rowb+gx1])
                    + fabsf(p0[HW+rowb+gx1]   - t0[HW+rowb+gx1])
                    + fabsf(p0[2*HW+rowb+gx1] - t0[2*HW+rowb+gx1]);
            }
            ring[k + 1] = r;
            if (k >= 3 && statAct) {                 // rows by..by+2
                s_acc  += r.x + r.y;
                ss_acc += r.x*r.x + r.y*r.y;
            }
        }
    }

    #pragma unroll
    for (int phase = 0; phase < TH / 4; ++phase) {
        if (loader) {
            #pragma unroll
            for (int j = 0; j < 4; ++j) {
                #pragma unroll
                for (int k = 0; k < 6; ++k) ring[k] = ring[k + 1];
                const int yr = by + 3 + phase * 4 + j;   // newest row
                const int gy = reflect_idx(yr, HGT);
                const int rowb = gy * WID;
                float2 r;
                if (inb) {
                    const int idx = rowb + hc;
                    float2 pa = *(const float2*)(p0 + idx);
                    float2 ta = *(const float2*)(t0 + idx);
                    float2 pb = *(const float2*)(p0 + HW + idx);
                    float2 tb = *(const float2*)(t0 + HW + idx);
                    float2 pc = *(const float2*)(p0 + 2*HW + idx);
                    float2 tc = *(const float2*)(t0 + 2*HW + idx);
                    r.x = fabsf(pa.x - ta.x) + fabsf(pb.x - tb.x) + fabsf(pc.x - tc.x);
                    r.y = fabsf(pa.y - ta.y) + fabsf(pb.y - tb.y) + fabsf(pc.y - tc.y);
                } else {
                    r.x = fabsf(p0[rowb+gx0]      - t0[rowb+gx0])
                        + fabsf(p0[HW+rowb+gx0]   - t0[HW+rowb+gx0])
                        + fabsf(p0[2*HW+rowb+gx0] - t0[2*HW+rowb+gx0]);
                    r.y = fabsf(p0[rowb+gx1]      - t0[rowb+gx1])
                        + fabsf(p0[HW+rowb+gx1]   - t0[HW+rowb+gx1])
                        + fabsf(p0[2*HW+rowb+gx1] - t0[2*HW+rowb+gx1]);
                }
                ring[6] = r;
                if (yr < by + TH && statAct) {           // rows by+3..by+15
                    s_acc  += r.x + r.y;
                    ss_acc += r.x*r.x + r.y*r.y;
                }
                float sx = 0.f, sy = 0.f, qx = 0.f, qy = 0.f;
                #pragma unroll
                for (int k = 0; k < 7; ++k) {
                    sx += ring[k].x; qx += ring[k].x * ring[k].x;
                    sy += ring[k].y; qy += ring[k].y * ring[k].y;
                }
                sVs[j][2*tid]     = sx;  sVs[j][2*tid + 1] = sy;
                sVq[j][2*tid]     = qx;  sVq[j][2*tid + 1] = qy;
                sC [j][2*tid]     = ring[3].x;
                sC [j][2*tid + 1] = ring[3].y;
            }
        }
        __syncthreads();
        if (outAct) {
            #pragma unroll
            for (int j = 0; j < 4; ++j) {
                const int h = 2 * tid;     // output cols bx+h, bx+h+1
                float ts[8], tq[8];
                #pragma unroll
                for (int k = 0; k < 8; ++k) {
                    ts[k] = sVs[j][h + 1 + k];
                    tq[k] = sVq[j][h + 1 + k];
                }
                float s0 = ts[0]+ts[1]+ts[2]+ts[3]+ts[4]+ts[5]+ts[6];
                float q0 = tq[0]+tq[1]+tq[2]+tq[3]+tq[4]+tq[5]+tq[6];
                float s1 = s0 - ts[0] + ts[7];
                float q1 = q0 - tq[0] + tq[7];
                float pw0 = (q0 - s0 * s0 * (1.0f/49.0f)) * (1.0f/48.0f);
                float pw1 = (q1 - s1 * s1 * (1.0f/49.0f)) * (1.0f/48.0f);
                wr_acc += pw0 * sC[j][h + 4] + pw1 * sC[j][h + 5];
            }
        }
        __syncthreads();
    }

    // Block reduce (5 warps) -> 3 double atomics.
    #pragma unroll
    for (int o = 16; o > 0; o >>= 1) {
        s_acc  += __shfl_down_sync(0xffffffffu, s_acc,  o);
        ss_acc += __shfl_down_sync(0xffffffffu, ss_acc, o);
        wr_acc += __shfl_down_sync(0xffffffffu, wr_acc, o);
    }
    const int lane = tid & 31, warp = tid >> 5;
    if (lane == 0) { red[0][warp] = s_acc; red[1][warp] = ss_acc; red[2][warp] = wr_acc; }
    __syncthreads();
    if (tid == 0) {
        float s = 0.f, ss = 0.f, wr = 0.f;
        #pragma unroll
        for (int w = 0; w < 5; ++w) { s += red[0][w]; ss += red[1][w]; wr += red[2][w]; }
        atomicAdd(&g_S[n],  (double)s);
        atomicAdd(&g_SS[n], (double)ss);
        atomicAdd(&g_WR[n], (double)wr);
        __threadfence();
        unsigned v = atomicAdd(&g_done, 1u);
        sLast = (v == NBLOCKS - 1);
    }
    __syncthreads();

    // Last block computes the loss (no separate finalize launch).
    if (sLast && warp == 0) {
        __threadfence();
        const double M = (double)HW;
        double t = 0.0;
        if (lane < NB) {
            double S  = *(volatile double*)&g_S[lane];
            double SS = *(volatile double*)&g_SS[lane];
            double WR = *(volatile double*)&g_WR[lane];
            double var = (SS - S * S / M) / (M - 1.0);
            float  pw  = powf((float)var, 0.2f);
            t = (double)pw * WR;
            g_S[lane] = 0.0; g_SS[lane] = 0.0; g_WR[lane] = 0.0;  // reset for replay
        }
        #pragma unroll
        for (int o = 16; o > 0; o >>= 1)
            t += __shfl_down_sync(0xffffffffu, t, o);
        if (lane == 0) {
            out[0] = (float)(t / ((double)NB * CH * HW));
            g_done = 0;
        }
    }
}

extern "C" void kernel_launch(void* const* d_in, const int* in_sizes, int n_in,
                              void* d_out, int out_size)
{
    const float* pred = (const float*)d_in[0];
    const float* targ = (const float*)d_in[1];
    float* out = (float*)d_out;

    dim3 grid(WID/TW, HGT/TH, NB);   // (2, 32, 16) = 1024 blocks
    fused_kernel<<<grid, NTHR>>>(pred, targ, out);
}